// round 13
// baseline (speedup 1.0000x reference)
#include <cuda_runtime.h>
#include <cuda_bf16.h>
#include <cuda_fp16.h>
#include <mma.h>
#include <math.h>
#include <cstdint>

using namespace nvcuda;

#define N_NODES  50000
#define TILE_M   64
#define GEMM_BLOCKS ((N_NODES + TILE_M - 1) / TILE_M)     // 782
#define N_PAD    (GEMM_BLOCKS * TILE_M)                   // 50048
#define N_EDGES  800000
#define E_TOT    (N_EDGES + N_NODES)
#define N_GRAPHS 256
#define FEAT     128
#define HID      64
#define HEADS    4
#define HH       (HID*HEADS)           // 256
#define OUTF     128
#define NEG_SLOPE 0.2f

// ---------------- scratch ----------------
__device__ __half g_h16[(size_t)N_PAD*HH];
__device__ float g_x[(size_t)N_PAD*HH];
__device__ __nv_bfloat16 g_wb_hi[3*HH*HH];
__device__ __nv_bfloat16 g_wb_lo[3*HH*HH];
__device__ float g_as[N_NODES*HEADS];
__device__ float g_ad[N_NODES*HEADS];
__device__ float g_pool[N_GRAPHS*HH];
__device__ int g_gstart[N_GRAPHS+1];
// CSR
__device__ int g_deg[N_NODES];
__device__ int g_rowptr[N_NODES+1];
__device__ int g_fill[N_NODES];
__device__ int g_colidx[E_TOT];

// ---------------- helpers ----------------
__device__ __forceinline__ void split2(float v, __nv_bfloat16& hi, __nv_bfloat16& lo) {
    hi = __float2bfloat16(v);
    lo = __float2bfloat16(v - __bfloat162float(hi));
}
__device__ __forceinline__ float warp_max(float v) {
    #pragma unroll
    for (int off = 16; off > 0; off >>= 1)
        v = fmaxf(v, __shfl_xor_sync(0xffffffffu, v, off));
    return v;
}
__device__ __forceinline__ float warp_sum(float v) {
    #pragma unroll
    for (int off = 16; off > 0; off >>= 1)
        v += __shfl_xor_sync(0xffffffffu, v, off);
    return v;
}
__device__ __forceinline__ void cp_async16(uint32_t saddr, const void* g) {
    asm volatile("cp.async.ca.shared.global [%0], [%1], 16;" :: "r"(saddr), "l"(g));
}
#define CP_COMMIT() asm volatile("cp.async.commit_group;" ::: "memory")
#define CP_WAIT0()  asm volatile("cp.async.wait_group 0;" ::: "memory")

// ---------------- fused prep: all 3 weight splits + deg zero ----------------
#define PREP_TOTAL ((FEAT + HH + HH) * HH)   // 163840
__global__ void prep_all_kernel(const float* __restrict__ W0,
                                const float* __restrict__ W1,
                                const float* __restrict__ W2) {
    int idx = blockIdx.x * blockDim.x + threadIdx.x;
    if (idx < N_NODES) g_deg[idx] = 0;
    if (idx >= PREP_TOTAL) return;
    const float* W;
    int layer, local;
    if (idx < FEAT * HH)              { W = W0; layer = 0; local = idx; }
    else if (idx < (FEAT + HH) * HH)  { W = W1; layer = 1; local = idx - FEAT * HH; }
    else                              { W = W2; layer = 2; local = idx - (FEAT + HH) * HH; }
    int k = local >> 8, n = local & (HH - 1);
    __nv_bfloat16 hi, lo;
    split2(W[local], hi, lo);
    g_wb_hi[layer * HH * HH + n * HH + k] = hi;
    g_wb_lo[layer * HH * HH + n * HH + k] = lo;
}

// ---------------- CSR build ----------------
__global__ void csr_hist_kernel(const int* __restrict__ ei) {
    int e = blockIdx.x * blockDim.x + threadIdx.x;
    if (e >= E_TOT) return;
    int dst = (e < N_EDGES) ? ei[N_EDGES + e] : e - N_EDGES;
    atomicAdd(&g_deg[dst], 1);
}
__global__ void csr_scan_kernel() {
    __shared__ int warp_sums[32];
    __shared__ int carry_sh;
    const int tid  = threadIdx.x;
    const int lane = tid & 31;
    const int wid  = tid >> 5;
    if (tid == 0) { carry_sh = 0; g_rowptr[0] = 0; }
    __syncthreads();
    for (int base = 0; base < N_NODES; base += 1024) {
        int v = (base + tid < N_NODES) ? g_deg[base + tid] : 0;
        int x = v;
        #pragma unroll
        for (int off = 1; off < 32; off <<= 1) {
            int y = __shfl_up_sync(0xffffffffu, x, off);
            if (lane >= off) x += y;
        }
        if (lane == 31) warp_sums[wid] = x;
        __syncthreads();
        if (wid == 0) {
            int w = warp_sums[lane];
            #pragma unroll
            for (int off = 1; off < 32; off <<= 1) {
                int y = __shfl_up_sync(0xffffffffu, w, off);
                if (lane >= off) w += y;
            }
            warp_sums[lane] = w;
        }
        __syncthreads();
        int incl = x + (wid > 0 ? warp_sums[wid - 1] : 0) + carry_sh;
        if (base + tid < N_NODES) {
            g_rowptr[base + tid + 1] = incl;
            g_fill[base + tid] = incl - v;
        }
        __syncthreads();
        if (tid == 1023) carry_sh = incl;
        __syncthreads();
    }
}
__global__ void csr_scatter_kernel(const int* __restrict__ ei) {
    int e = blockIdx.x * blockDim.x + threadIdx.x;
    if (e >= E_TOT) return;
    int src, dst;
    if (e < N_EDGES) { src = ei[e]; dst = ei[N_EDGES + e]; }
    else             { src = dst = e - N_EDGES; }
    int pos = atomicAdd(&g_fill[dst], 1);
    g_colidx[pos] = src;
}

// ---------------- tensor-core GEMM (64x256), 8 warps, warp tile 32x64,
//                  KCHUNK=16 double-buffered (cp.async B), warp-local epilogue, 2 CTAs/SM ----------
#define LDP 24
#define ABUF (TILE_M * LDP * 2)          // 3072
#define BBUF (HH * LDP * 2)              // 12288
#define STGBUF (2*ABUF + 2*BBUF)         // 30720 per stage-buffer
#define OFF_A_HI(d) ((d) * STGBUF)
#define OFF_A_LO(d) ((d) * STGBUF + ABUF)
#define OFF_B_HI(d) ((d) * STGBUF + 2*ABUF)
#define OFF_B_LO(d) ((d) * STGBUF + 2*ABUF + BBUF)
#define OFF_WT      (2 * STGBUF)         // 61440: per-warp 16x18 f32 tiles
#define WT_STRIDE   18
#define WT_BYTES    (16 * WT_STRIDE * 4) // 1152
#define SMEM_DYN    (OFF_WT + 8 * WT_BYTES)   // 70656
__global__ __launch_bounds__(256, 2)
void gat_gemm_kernel(const float* __restrict__ A_in, int layer,
                     const float* __restrict__ a_s, const float* __restrict__ a_d,
                     int K) {
    extern __shared__ char dyn[];
    __shared__ float as_sh[HH], ad_sh[HH];

    const int tid  = threadIdx.x;
    const int wid  = tid >> 5;         // 0..7
    const int lane = tid & 31;
    const int mw   = wid & 1;          // row group (32 rows)
    const int nw   = wid >> 1;         // col group (64 cols) == head
    const int rowBase = blockIdx.x * TILE_M;

    const float* __restrict__ A = A_in ? A_in : g_x;
    const __nv_bfloat16* __restrict__ whi = g_wb_hi + (size_t)layer * HH * HH;
    const __nv_bfloat16* __restrict__ wlo = g_wb_lo + (size_t)layer * HH * HH;

    as_sh[tid] = a_s[tid];
    ad_sh[tid] = a_d[tid];

    const uint32_t dynb = (uint32_t)__cvta_generic_to_shared(dyn);

    // staging roles (per 16-k stage)
    const int ar  = tid >> 2;            // A row 0..63
    const int ac  = (tid & 3) * 4;       // 4 floats per thread
    const bool aOk = (rowBase + ar) < N_NODES;
    const float* aptr = A + (size_t)(rowBase + ar) * K + ac;
    const uint32_t aRowOff = ar * 48 + ac * 2;   // bytes
    const int bn  = tid;                 // B row 0..255
    const __nv_bfloat16* bhp = whi + bn * HH;
    const __nv_bfloat16* blp = wlo + bn * HH;
    const uint32_t bRowOff = bn * 48;    // bytes

    wmma::fragment<wmma::accumulator, 16, 16, 16, float> acc[2][4];
    #pragma unroll
    for (int i = 0; i < 2; i++)
        #pragma unroll
        for (int j = 0; j < 4; j++)
            wmma::fill_fragment(acc[i][j], 0.f);

    const int nstages = K >> 4;

    auto stageA = [&](int d, const float4& p) {
        __nv_bfloat16 h0, l0, h1, l1, h2, l2, h3, l3;
        split2(p.x, h0, l0); split2(p.y, h1, l1);
        split2(p.z, h2, l2); split2(p.w, h3, l3);
        uint2 vh, vl;
        vh.x = ((uint32_t)*(uint16_t*)&h1 << 16) | *(uint16_t*)&h0;
        vh.y = ((uint32_t)*(uint16_t*)&h3 << 16) | *(uint16_t*)&h2;
        vl.x = ((uint32_t)*(uint16_t*)&l1 << 16) | *(uint16_t*)&l0;
        vl.y = ((uint32_t)*(uint16_t*)&l3 << 16) | *(uint16_t*)&l2;
        *(uint2*)(dyn + OFF_A_HI(d) + aRowOff) = vh;
        *(uint2*)(dyn + OFF_A_LO(d) + aRowOff) = vl;
    };
    auto issueB = [&](int d, int k0) {
        cp_async16(dynb + OFF_B_HI(d) + bRowOff,      bhp + k0);
        cp_async16(dynb + OFF_B_HI(d) + bRowOff + 16, bhp + k0 + 8);
        cp_async16(dynb + OFF_B_LO(d) + bRowOff,      blp + k0);
        cp_async16(dynb + OFF_B_LO(d) + bRowOff + 16, blp + k0 + 8);
        CP_COMMIT();
    };

    // prologue: stage 0
    float4 pa = aOk ? *(const float4*)(aptr) : make_float4(0.f,0.f,0.f,0.f);
    issueB(0, 0);
    stageA(0, pa);
    if (nstages > 1)
        pa = aOk ? *(const float4*)(aptr + 16) : make_float4(0.f,0.f,0.f,0.f);

    for (int c = 0; c < nstages; c++) {
        const int d = c & 1;
        CP_WAIT0();
        __syncthreads();
        if (c + 1 < nstages) {
            issueB(d ^ 1, (c + 1) << 4);
            stageA(d ^ 1, pa);
            if (c + 2 < nstages)
                pa = aOk ? *(const float4*)(aptr + ((c + 2) << 4)) : make_float4(0.f,0.f,0.f,0.f);
        }
        const __nv_bfloat16* Ah = (const __nv_bfloat16*)(dyn + OFF_A_HI(d));
        const __nv_bfloat16* Al = (const __nv_bfloat16*)(dyn + OFF_A_LO(d));
        const __nv_bfloat16* Bh = (const __nv_bfloat16*)(dyn + OFF_B_HI(d));
        const __nv_bfloat16* Bl = (const __nv_bfloat16*)(dyn + OFF_B_LO(d));

        wmma::fragment<wmma::matrix_a, 16, 16, 16, __nv_bfloat16, wmma::row_major> a_hi[2], a_lo[2];
        #pragma unroll
        for (int i = 0; i < 2; i++) {
            wmma::load_matrix_sync(a_hi[i], Ah + (mw * 32 + i * 16) * LDP, LDP);
            wmma::load_matrix_sync(a_lo[i], Al + (mw * 32 + i * 16) * LDP, LDP);
        }
        #pragma unroll
        for (int j = 0; j < 4; j++) {
            wmma::fragment<wmma::matrix_b, 16, 16, 16, __nv_bfloat16, wmma::col_major> b_hi, b_lo;
            wmma::load_matrix_sync(b_hi, Bh + (nw * 64 + j * 16) * LDP, LDP);
            wmma::load_matrix_sync(b_lo, Bl + (nw * 64 + j * 16) * LDP, LDP);
            #pragma unroll
            for (int i = 0; i < 2; i++) {
                wmma::mma_sync(acc[i][j], a_hi[i], b_hi, acc[i][j]);
                wmma::mma_sync(acc[i][j], a_hi[i], b_lo, acc[i][j]);
                wmma::mma_sync(acc[i][j], a_lo[i], b_hi, acc[i][j]);
            }
        }
    }

    // ---- warp-local epilogue: per-tile smem bounce -> alpha dots + fp16 pack ----
    float* wt = (float*)(dyn + OFF_WT + wid * WT_BYTES);
    const int r2 = lane >> 1;            // row within 16-row tile
    const int c0 = (lane & 1) * 8;       // col half
    float asum[2] = {0.f, 0.f}, adsum[2] = {0.f, 0.f};

    #pragma unroll
    for (int j = 0; j < 4; j++) {
        #pragma unroll
        for (int i = 0; i < 2; i++) {
            wmma::store_matrix_sync(wt, acc[i][j], WT_STRIDE, wmma::mem_row_major);
            __syncwarp();
            const float* rowp = wt + r2 * WT_STRIDE + c0;
            const int colg = nw * 64 + j * 16 + c0;
            const float* sp = as_sh + colg;
            const float* dp = ad_sh + colg;
            float vs = 0.f, vd = 0.f;
            uint32_t pk[4];
            #pragma unroll
            for (int k = 0; k < 8; k += 2) {
                float v0 = rowp[k], v1 = rowp[k + 1];
                vs += v0 * sp[k] + v1 * sp[k + 1];
                vd += v0 * dp[k] + v1 * dp[k + 1];
                __half2 p = __floats2half2_rn(v0, v1);
                pk[k >> 1] = *(uint32_t*)&p;
            }
            asum[i] += vs;
            adsum[i] += vd;
            int row = rowBase + mw * 32 + i * 16 + r2;
            *(uint4*)(g_h16 + (size_t)row * HH + colg) = make_uint4(pk[0], pk[1], pk[2], pk[3]);
            __syncwarp();
        }
    }
    #pragma unroll
    for (int i = 0; i < 2; i++) {
        float s = asum[i] + __shfl_xor_sync(0xffffffffu, asum[i], 1);
        float d = adsum[i] + __shfl_xor_sync(0xffffffffu, adsum[i], 1);
        if ((lane & 1) == 0) {
            int row = rowBase + mw * 32 + i * 16 + r2;
            if (row < N_NODES) {
                g_as[row * HEADS + nw] = s;
                g_ad[row * HEADS + nw] = d;
            }
        }
    }
}

// ---------------- warp-per-node flash softmax + aggregation (fp16 gathers) ----------------
#define WPB 8
__global__ __launch_bounds__(256)
void agg_kernel(const float* __restrict__ bias) {
    const int wrp  = threadIdx.x >> 5;
    const int lane = threadIdx.x & 31;
    const int node = blockIdx.x * WPB + wrp;
    if (node >= N_NODES) return;

    __shared__ float s_al[WPB][32 * 4];
    __shared__ int   s_src[WPB][32];

    const int start = g_rowptr[node];
    const int end   = g_rowptr[node + 1];

    const float4 ad4 = *(const float4*)(g_ad + node * HEADS);

    const int head = lane >> 3;
    float m0 = -INFINITY, m1 = -INFINITY, m2 = -INFINITY, m3 = -INFINITY;
    float s0 = 0.f, s1 = 0.f, s2 = 0.f, s3 = 0.f;
    float acc[8] = {0.f, 0.f, 0.f, 0.f, 0.f, 0.f, 0.f, 0.f};

    for (int c0 = start; c0 < end; c0 += 32) {
        const int len = min(32, end - c0);

        float e0 = -INFINITY, e1 = -INFINITY, e2 = -INFINITY, e3 = -INFINITY;
        if (lane < len) {
            int s = g_colidx[c0 + lane];
            s_src[wrp][lane] = s;
            float4 as4 = *(const float4*)(g_as + s * HEADS);
            e0 = as4.x + ad4.x; e0 = (e0 > 0.f) ? e0 : NEG_SLOPE * e0;
            e1 = as4.y + ad4.y; e1 = (e1 > 0.f) ? e1 : NEG_SLOPE * e1;
            e2 = as4.z + ad4.z; e2 = (e2 > 0.f) ? e2 : NEG_SLOPE * e2;
            e3 = as4.w + ad4.w; e3 = (e3 > 0.f) ? e3 : NEG_SLOPE * e3;
        }
        float n0 = fmaxf(m0, warp_max(e0));
        float n1 = fmaxf(m1, warp_max(e1));
        float n2 = fmaxf(m2, warp_max(e2));
        float n3 = fmaxf(m3, warp_max(e3));
        float sc0 = expf(m0 - n0), sc1 = expf(m1 - n1);
        float sc2 = expf(m2 - n2), sc3 = expf(m3 - n3);
        m0 = n0; m1 = n1; m2 = n2; m3 = n3;

        float q0 = (lane < len) ? expf(e0 - m0) : 0.f;
        float q1 = (lane < len) ? expf(e1 - m1) : 0.f;
        float q2 = (lane < len) ? expf(e2 - m2) : 0.f;
        float q3 = (lane < len) ? expf(e3 - m3) : 0.f;
        s_al[wrp][lane * 4 + 0] = q0;
        s_al[wrp][lane * 4 + 1] = q1;
        s_al[wrp][lane * 4 + 2] = q2;
        s_al[wrp][lane * 4 + 3] = q3;
        s0 = s0 * sc0 + warp_sum(q0);
        s1 = s1 * sc1 + warp_sum(q1);
        s2 = s2 * sc2 + warp_sum(q2);
        s3 = s3 * sc3 + warp_sum(q3);

        float accsc = (head == 0) ? sc0 : (head == 1) ? sc1 : (head == 2) ? sc2 : sc3;
        #pragma unroll
        for (int k = 0; k < 8; k++) acc[k] *= accsc;
        __syncwarp();

        #pragma unroll 4
        for (int j = 0; j < len; j++) {
            float a = s_al[wrp][j * 4 + head];
            uint4 u = *(const uint4*)(g_h16 + (size_t)s_src[wrp][j] * HH + lane * 8);
            float2 f0 = __half22float2(*(__half2*)&u.x);
            float2 f1 = __half22float2(*(__half2*)&u.y);
            float2 f2 = __half22float2(*(__half2*)&u.z);
            float2 f3 = __half22float2(*(__half2*)&u.w);
            acc[0] += a * f0.x; acc[1] += a * f0.y;
            acc[2] += a * f1.x; acc[3] += a * f1.y;
            acc[4] += a * f2.x; acc[5] += a * f2.y;
            acc[6] += a * f3.x; acc[7] += a * f3.y;
        }
        __syncwarp();
    }

    float rs = 1.f / ((head == 0) ? s0 : (head == 1) ? s1 : (head == 2) ? s2 : s3);
    const int f0 = lane * 8;
    size_t oi = (size_t)node * HH + f0;
    float o[8];
    #pragma unroll
    for (int k = 0; k < 8; k++) {
        float v = acc[k] * rs + bias[f0 + k];
        o[k] = (v > 0.f) ? v : expm1f(v);
    }
    *(float4*)(g_x + oi)     = make_float4(o[0], o[1], o[2], o[3]);
    *(float4*)(g_x + oi + 4) = make_float4(o[4], o[5], o[6], o[7]);
}

// ---------------- pooling ----------------
__global__ void graph_bounds_kernel(const int* __restrict__ batch) {
    int n = blockIdx.x * blockDim.x + threadIdx.x;
    if (n >= N_NODES) return;
    int b = batch[n];
    if (n == 0) {
        for (int g = 0; g <= b; g++) g_gstart[g] = 0;
    } else {
        int bp = batch[n - 1];
        for (int g = bp + 1; g <= b; g++) g_gstart[g] = n;
    }
    if (n == N_NODES - 1) {
        for (int g = b + 1; g <= N_GRAPHS; g++) g_gstart[g] = N_NODES;
    }
}
__global__ void pool_mean_kernel() {
    int g = blockIdx.x, f = threadIdx.x;
    int s = g_gstart[g], e = g_gstart[g + 1];
    float acc = 0.f;
    for (int n = s; n < e; n++)
        acc += g_x[(size_t)n * HH + f];
    g_pool[g * HH + f] = acc / (float)max(e - s, 1);
}

// ---------------- final ----------------
__global__ void final_kernel(const float* __restrict__ Wf, const float* __restrict__ bf,
                             float* __restrict__ out) {
    __shared__ float gs[HH];
    __shared__ float red[OUTF];
    int g = blockIdx.x;
    int t = threadIdx.x;
    for (int i = t; i < HH; i += OUTF) gs[i] = g_pool[g * HH + i];
    __syncthreads();
    float acc = bf[t];
    #pragma unroll 8
    for (int k = 0; k < HH; k++)
        acc += gs[k] * Wf[(size_t)k * OUTF + t];
    red[t] = acc * acc;
    __syncthreads();
    #pragma unroll
    for (int off = 64; off > 0; off >>= 1) {
        if (t < off) red[t] += red[t + off];
        __syncthreads();
    }
    float norm = fmaxf(sqrtf(red[0]), 1e-12f);
    out[(size_t)g * OUTF + t] = acc / norm;
}

// ---------------- host orchestration ----------------
extern "C" void kernel_launch(void* const* d_in, const int* in_sizes, int n_in,
                              void* d_out, int out_size) {
    const float* x     = (const float*)d_in[0];
    const int*   ei    = (const int*)d_in[1];
    const int*   batch = (const int*)d_in[2];
    const float* W[3]  = {(const float*)d_in[3],  (const float*)d_in[7],  (const float*)d_in[11]};
    const float* AS[3] = {(const float*)d_in[4],  (const float*)d_in[8],  (const float*)d_in[12]};
    const float* AD[3] = {(const float*)d_in[5],  (const float*)d_in[9],  (const float*)d_in[13]};
    const float* Bb[3] = {(const float*)d_in[6],  (const float*)d_in[10], (const float*)d_in[14]};
    const float* Wf = (const float*)d_in[15];
    const float* bf = (const float*)d_in[16];
    float* out = (float*)d_out;

    static cudaStream_t s2 = [] {
        cudaStream_t s; cudaStreamCreateWithFlags(&s, cudaStreamNonBlocking); return s;
    }();
    static cudaEvent_t eFork = [] {
        cudaEvent_t e; cudaEventCreateWithFlags(&e, cudaEventDisableTiming); return e;
    }();
    static cudaEvent_t eW = [] {
        cudaEvent_t e; cudaEventCreateWithFlags(&e, cudaEventDisableTiming); return e;
    }();
    static cudaEvent_t eCSR = [] {
        cudaEvent_t e; cudaEventCreateWithFlags(&e, cudaEventDisableTiming); return e;
    }();
    static cudaEvent_t eGB = [] {
        cudaEvent_t e; cudaEventCreateWithFlags(&e, cudaEventDisableTiming); return e;
    }();
    static bool attr_set = [] {
        cudaFuncSetAttribute(gat_gemm_kernel,
                             cudaFuncAttributeMaxDynamicSharedMemorySize, SMEM_DYN);
        return true;
    }();
    (void)attr_set;

    const int threads = 256;
    const int edge_blocks = (E_TOT + threads - 1) / threads;
    const int agg_blocks  = (N_NODES + WPB - 1) / WPB;

    cudaEventRecord(eFork, 0);
    cudaStreamWaitEvent(s2, eFork, 0);

    // launches 1-3 (side stream)
    prep_all_kernel<<<(PREP_TOTAL + threads - 1) / threads, threads, 0, s2>>>(W[0], W[1], W[2]);
    cudaEventRecord(eW, s2);
    csr_hist_kernel<<<edge_blocks, threads, 0, s2>>>(ei);
    csr_scan_kernel<<<1, 1024, 0, s2>>>();

    // launch 4: gemm layer 0 (profiler capture target)
    cudaStreamWaitEvent(0, eW, 0);
    gat_gemm_kernel<<<GEMM_BLOCKS, 256, SMEM_DYN>>>(x, 0, AS[0], AD[0], FEAT);

    // launches 5-6 (side stream)
    csr_scatter_kernel<<<edge_blocks, threads, 0, s2>>>(ei);
    cudaEventRecord(eCSR, s2);
    graph_bounds_kernel<<<(N_NODES + threads - 1) / threads, threads, 0, s2>>>(batch);
    cudaEventRecord(eGB, s2);

    cudaStreamWaitEvent(0, eCSR, 0);
    agg_kernel<<<agg_blocks, 256>>>(Bb[0]);

    gat_gemm_kernel<<<GEMM_BLOCKS, 256, SMEM_DYN>>>(nullptr, 1, AS[1], AD[1], HH);
    agg_kernel<<<agg_blocks, 256>>>(Bb[1]);

    gat_gemm_kernel<<<GEMM_BLOCKS, 256, SMEM_DYN>>>(nullptr, 2, AS[2], AD[2], HH);
    agg_kernel<<<agg_blocks, 256>>>(Bb[2]);

    cudaStreamWaitEvent(0, eGB, 0);
    pool_mean_kernel<<<N_GRAPHS, 256>>>();
    final_kernel<<<N_GRAPHS, OUTF>>>(Wf, bf, out);
}

// round 14
// speedup vs baseline: 1.3351x; 1.3351x over previous
#include <cuda_runtime.h>
#include <cuda_fp16.h>
#include <mma.h>
#include <math.h>
#include <cstdint>

using namespace nvcuda;

#define N_NODES  50000
#define TILE_M   128
#define GEMM_BLOCKS ((N_NODES + TILE_M - 1) / TILE_M)     // 392
#define N_PAD    (GEMM_BLOCKS * TILE_M)                   // 50176
#define N_EDGES  800000
#define E_TOT    (N_EDGES + N_NODES)
#define N_GRAPHS 256
#define FEAT     128
#define HID      64
#define HEADS    4
#define HH       (HID*HEADS)           // 256
#define OUTF     128
#define NEG_SLOPE 0.2f

// ---------------- scratch ----------------
__device__ __half g_h16[(size_t)N_PAD*HH];   // fp16 messages (agg gather source)
__device__ float g_x[(size_t)N_PAD*HH];      // layer output / next GEMM input
__device__ __half g_w16[3*HH*HH];            // fp16 weights, [n][k], row stride 256
__device__ float g_as[N_NODES*HEADS];
__device__ float g_ad[N_NODES*HEADS];
__device__ float g_pool[N_GRAPHS*HH];
__device__ int g_gstart[N_GRAPHS+1];
// CSR
__device__ int g_deg[N_NODES];
__device__ int g_rowptr[N_NODES+1];
__device__ int g_fill[N_NODES];
__device__ int g_colidx[E_TOT];

// ---------------- helpers ----------------
__device__ __forceinline__ float warp_max(float v) {
    #pragma unroll
    for (int off = 16; off > 0; off >>= 1)
        v = fmaxf(v, __shfl_xor_sync(0xffffffffu, v, off));
    return v;
}
__device__ __forceinline__ float warp_sum(float v) {
    #pragma unroll
    for (int off = 16; off > 0; off >>= 1)
        v += __shfl_xor_sync(0xffffffffu, v, off);
    return v;
}
__device__ __forceinline__ void cp_async16(uint32_t saddr, const void* g) {
    asm volatile("cp.async.ca.shared.global [%0], [%1], 16;" :: "r"(saddr), "l"(g));
}
#define CP_COMMIT() asm volatile("cp.async.commit_group;" ::: "memory")
#define CP_WAIT0()  asm volatile("cp.async.wait_group 0;" ::: "memory")

// ---------------- fused prep: all 3 weight fp16 conversions + deg zero ----------------
#define PREP_TOTAL ((FEAT + HH + HH) * HH)   // 163840
__global__ void prep_all_kernel(const float* __restrict__ W0,
                                const float* __restrict__ W1,
                                const float* __restrict__ W2) {
    int idx = blockIdx.x * blockDim.x + threadIdx.x;
    if (idx < N_NODES) g_deg[idx] = 0;
    if (idx >= PREP_TOTAL) return;
    const float* W;
    int layer, local;
    if (idx < FEAT * HH)              { W = W0; layer = 0; local = idx; }
    else if (idx < (FEAT + HH) * HH)  { W = W1; layer = 1; local = idx - FEAT * HH; }
    else                              { W = W2; layer = 2; local = idx - (FEAT + HH) * HH; }
    int k = local >> 8, n = local & (HH - 1);
    g_w16[layer * HH * HH + n * HH + k] = __float2half_rn(W[local]);
}

// ---------------- CSR build ----------------
__global__ void csr_hist_kernel(const int* __restrict__ ei) {
    int e = blockIdx.x * blockDim.x + threadIdx.x;
    if (e >= E_TOT) return;
    int dst = (e < N_EDGES) ? ei[N_EDGES + e] : e - N_EDGES;
    atomicAdd(&g_deg[dst], 1);
}
__global__ void csr_scan_kernel() {
    __shared__ int warp_sums[32];
    __shared__ int carry_sh;
    const int tid  = threadIdx.x;
    const int lane = tid & 31;
    const int wid  = tid >> 5;
    if (tid == 0) { carry_sh = 0; g_rowptr[0] = 0; }
    __syncthreads();
    for (int base = 0; base < N_NODES; base += 1024) {
        int v = (base + tid < N_NODES) ? g_deg[base + tid] : 0;
        int x = v;
        #pragma unroll
        for (int off = 1; off < 32; off <<= 1) {
            int y = __shfl_up_sync(0xffffffffu, x, off);
            if (lane >= off) x += y;
        }
        if (lane == 31) warp_sums[wid] = x;
        __syncthreads();
        if (wid == 0) {
            int w = warp_sums[lane];
            #pragma unroll
            for (int off = 1; off < 32; off <<= 1) {
                int y = __shfl_up_sync(0xffffffffu, w, off);
                if (lane >= off) w += y;
            }
            warp_sums[lane] = w;
        }
        __syncthreads();
        int incl = x + (wid > 0 ? warp_sums[wid - 1] : 0) + carry_sh;
        if (base + tid < N_NODES) {
            g_rowptr[base + tid + 1] = incl;
            g_fill[base + tid] = incl - v;
        }
        __syncthreads();
        if (tid == 1023) carry_sh = incl;
        __syncthreads();
    }
}
__global__ void csr_scatter_kernel(const int* __restrict__ ei) {
    int e = blockIdx.x * blockDim.x + threadIdx.x;
    if (e >= E_TOT) return;
    int src, dst;
    if (e < N_EDGES) { src = ei[e]; dst = ei[N_EDGES + e]; }
    else             { src = dst = e - N_EDGES; }
    int pos = atomicAdd(&g_fill[dst], 1);
    g_colidx[pos] = src;
}

// ---------------- fp16 tensor-core GEMM (128x256), 16 warps, warp tile 32x64,
//                  KCHUNK=32 double-buffered (cp.async B), smem C epilogue ----------------
#define LDP 40                            // 80-byte rows
#define LDC 264
#define SMEM_DYN (TILE_M * LDC * 4)       // 135168; staging (2x30720) overlays
#define ABUF 10240                        // 128*40*2
#define BBUF 20480                        // 256*40*2
#define STGBUF (ABUF + BBUF)              // 30720
#define OFF_A(d) ((d) * STGBUF)
#define OFF_B(d) ((d) * STGBUF + ABUF)
__global__ __launch_bounds__(512)
void gat_gemm_kernel(const float* __restrict__ A_in, int layer,
                     const float* __restrict__ a_s, const float* __restrict__ a_d,
                     int K) {
    extern __shared__ char dyn[];
    float* Csm = (float*)(dyn);
    __shared__ float as_sh[HH], ad_sh[HH];

    const int tid = threadIdx.x;
    const int wid = tid >> 5;          // 0..15
    const int mw  = wid & 3;           // row group (32 rows)
    const int nw  = wid >> 2;          // col group (64 cols)
    const int rowBase = blockIdx.x * TILE_M;

    const float* __restrict__ A = A_in ? A_in : g_x;
    const __half* __restrict__ w16 = g_w16 + (size_t)layer * HH * HH;

    if (tid < HH) { as_sh[tid] = a_s[tid]; ad_sh[tid] = a_d[tid]; }

    const uint32_t dynb = (uint32_t)__cvta_generic_to_shared(dyn);

    // staging roles (per 32-k stage)
    const int ar  = tid >> 2;            // A row 0..127
    const int ac  = (tid & 3) * 8;       // 8 floats within the 32-k chunk
    const bool aOk = (rowBase + ar) < N_NODES;
    const float* aptr = A + (size_t)(rowBase + ar) * K + ac;
    const uint32_t aRowOff = ar * 80 + ac * 2;     // bytes
    const int bn  = tid >> 1;            // B row 0..255
    const int bo  = (tid & 1) * 16;      // half offset within chunk
    const __half* bp = w16 + bn * HH + bo;
    const uint32_t bRowOff = bn * 80 + bo * 2;     // bytes

    wmma::fragment<wmma::accumulator, 16, 16, 16, float> acc[2][4];
    #pragma unroll
    for (int i = 0; i < 2; i++)
        #pragma unroll
        for (int j = 0; j < 4; j++)
            wmma::fill_fragment(acc[i][j], 0.f);

    const int nstages = K >> 5;

    auto stageA = [&](int d, const float4& p0, const float4& p1) {
        __half2 h0 = __floats2half2_rn(p0.x, p0.y);
        __half2 h1 = __floats2half2_rn(p0.z, p0.w);
        __half2 h2 = __floats2half2_rn(p1.x, p1.y);
        __half2 h3 = __floats2half2_rn(p1.z, p1.w);
        uint4 v;
        v.x = *(uint32_t*)&h0; v.y = *(uint32_t*)&h1;
        v.z = *(uint32_t*)&h2; v.w = *(uint32_t*)&h3;
        *(uint4*)(dyn + OFF_A(d) + aRowOff) = v;
    };
    auto issueB = [&](int d, int k0) {
        cp_async16(dynb + OFF_B(d) + bRowOff,      bp + k0);
        cp_async16(dynb + OFF_B(d) + bRowOff + 16, bp + k0 + 8);
        CP_COMMIT();
    };

    // prologue: stage 0
    float4 pa0 = aOk ? *(const float4*)(aptr)     : make_float4(0.f,0.f,0.f,0.f);
    float4 pa1 = aOk ? *(const float4*)(aptr + 4) : make_float4(0.f,0.f,0.f,0.f);
    issueB(0, 0);
    stageA(0, pa0, pa1);
    if (nstages > 1) {
        pa0 = aOk ? *(const float4*)(aptr + 32)     : make_float4(0.f,0.f,0.f,0.f);
        pa1 = aOk ? *(const float4*)(aptr + 32 + 4) : make_float4(0.f,0.f,0.f,0.f);
    }

    for (int c = 0; c < nstages; c++) {
        const int d = c & 1;
        CP_WAIT0();
        __syncthreads();
        if (c + 1 < nstages) {
            issueB(d ^ 1, (c + 1) << 5);
            stageA(d ^ 1, pa0, pa1);
            if (c + 2 < nstages) {
                int k2 = (c + 2) << 5;
                pa0 = aOk ? *(const float4*)(aptr + k2)     : make_float4(0.f,0.f,0.f,0.f);
                pa1 = aOk ? *(const float4*)(aptr + k2 + 4) : make_float4(0.f,0.f,0.f,0.f);
            }
        }
        const __half* Ah = (const __half*)(dyn + OFF_A(d));
        const __half* Bh = (const __half*)(dyn + OFF_B(d));

        #pragma unroll
        for (int kk = 0; kk < 2; kk++) {
            wmma::fragment<wmma::matrix_a, 16, 16, 16, __half, wmma::row_major> a[2];
            #pragma unroll
            for (int i = 0; i < 2; i++)
                wmma::load_matrix_sync(a[i], Ah + (mw * 32 + i * 16) * LDP + kk * 16, LDP);
            #pragma unroll
            for (int j = 0; j < 4; j++) {
                wmma::fragment<wmma::matrix_b, 16, 16, 16, __half, wmma::col_major> b;
                wmma::load_matrix_sync(b, Bh + (nw * 64 + j * 16) * LDP + kk * 16, LDP);
                #pragma unroll
                for (int i = 0; i < 2; i++)
                    wmma::mma_sync(acc[i][j], a[i], b, acc[i][j]);
            }
        }
    }
    __syncthreads();   // staging reads done before C overlays

    #pragma unroll
    for (int i = 0; i < 2; i++)
        #pragma unroll
        for (int j = 0; j < 4; j++) {
            float* cp = Csm + (size_t)(mw * 32 + i * 16) * LDC + nw * 64 + j * 16;
            wmma::store_matrix_sync(cp, acc[i][j], LDC, wmma::mem_row_major);
        }
    __syncthreads();

    // epilogue: alphas dot + fp16 message pack
    int rl = tid >> 2;
    int hd = tid & 3;
    int r  = rowBase + rl;
    if (r < N_NODES) {
        const float* hp = Csm + (size_t)rl * LDC + hd * HID;
        __half* h16p = g_h16 + (size_t)r * HH + hd * HID;
        const float* sp = as_sh + hd * HID;
        const float* dp = ad_sh + hd * HID;
        float vs = 0.f, vd = 0.f;
        #pragma unroll
        for (int c = 0; c < HID; c += 4) {
            float4 v = *(const float4*)(hp + c);
            vs += v.x * sp[c] + v.y * sp[c+1] + v.z * sp[c+2] + v.w * sp[c+3];
            vd += v.x * dp[c] + v.y * dp[c+1] + v.z * dp[c+2] + v.w * dp[c+3];
            uint2 pk;
            __half2 p0 = __floats2half2_rn(v.x, v.y);
            __half2 p1 = __floats2half2_rn(v.z, v.w);
            pk.x = *(uint32_t*)&p0;
            pk.y = *(uint32_t*)&p1;
            *(uint2*)(h16p + c) = pk;
        }
        g_as[r * HEADS + hd] = vs;
        g_ad[r * HEADS + hd] = vd;
    }
}

// ---------------- warp-per-node flash softmax + aggregation (fp16 gathers) ----------------
#define WPB 8
__global__ __launch_bounds__(256)
void agg_kernel(const float* __restrict__ bias) {
    const int wrp  = threadIdx.x >> 5;
    const int lane = threadIdx.x & 31;
    const int node = blockIdx.x * WPB + wrp;
    if (node >= N_NODES) return;

    __shared__ float s_al[WPB][32 * 4];
    __shared__ int   s_src[WPB][32];

    const int start = g_rowptr[node];
    const int end   = g_rowptr[node + 1];

    const float4 ad4 = *(const float4*)(g_ad + node * HEADS);

    const int head = lane >> 3;
    float m0 = -INFINITY, m1 = -INFINITY, m2 = -INFINITY, m3 = -INFINITY;
    float s0 = 0.f, s1 = 0.f, s2 = 0.f, s3 = 0.f;
    float acc[8] = {0.f, 0.f, 0.f, 0.f, 0.f, 0.f, 0.f, 0.f};

    for (int c0 = start; c0 < end; c0 += 32) {
        const int len = min(32, end - c0);

        float e0 = -INFINITY, e1 = -INFINITY, e2 = -INFINITY, e3 = -INFINITY;
        if (lane < len) {
            int s = g_colidx[c0 + lane];
            s_src[wrp][lane] = s;
            float4 as4 = *(const float4*)(g_as + s * HEADS);
            e0 = as4.x + ad4.x; e0 = (e0 > 0.f) ? e0 : NEG_SLOPE * e0;
            e1 = as4.y + ad4.y; e1 = (e1 > 0.f) ? e1 : NEG_SLOPE * e1;
            e2 = as4.z + ad4.z; e2 = (e2 > 0.f) ? e2 : NEG_SLOPE * e2;
            e3 = as4.w + ad4.w; e3 = (e3 > 0.f) ? e3 : NEG_SLOPE * e3;
        }
        float n0 = fmaxf(m0, warp_max(e0));
        float n1 = fmaxf(m1, warp_max(e1));
        float n2 = fmaxf(m2, warp_max(e2));
        float n3 = fmaxf(m3, warp_max(e3));
        float sc0 = expf(m0 - n0), sc1 = expf(m1 - n1);
        float sc2 = expf(m2 - n2), sc3 = expf(m3 - n3);
        m0 = n0; m1 = n1; m2 = n2; m3 = n3;

        float q0 = (lane < len) ? expf(e0 - m0) : 0.f;
        float q1 = (lane < len) ? expf(e1 - m1) : 0.f;
        float q2 = (lane < len) ? expf(e2 - m2) : 0.f;
        float q3 = (lane < len) ? expf(e3 - m3) : 0.f;
        s_al[wrp][lane * 4 + 0] = q0;
        s_al[wrp][lane * 4 + 1] = q1;
        s_al[wrp][lane * 4 + 2] = q2;
        s_al[wrp][lane * 4 + 3] = q3;
        s0 = s0 * sc0 + warp_sum(q0);
        s1 = s1 * sc1 + warp_sum(q1);
        s2 = s2 * sc2 + warp_sum(q2);
        s3 = s3 * sc3 + warp_sum(q3);

        float accsc = (head == 0) ? sc0 : (head == 1) ? sc1 : (head == 2) ? sc2 : sc3;
        #pragma unroll
        for (int k = 0; k < 8; k++) acc[k] *= accsc;
        __syncwarp();

        #pragma unroll 4
        for (int j = 0; j < len; j++) {
            float a = s_al[wrp][j * 4 + head];
            uint4 u = *(const uint4*)(g_h16 + (size_t)s_src[wrp][j] * HH + lane * 8);
            float2 f0 = __half22float2(*(__half2*)&u.x);
            float2 f1 = __half22float2(*(__half2*)&u.y);
            float2 f2 = __half22float2(*(__half2*)&u.z);
            float2 f3 = __half22float2(*(__half2*)&u.w);
            acc[0] += a * f0.x; acc[1] += a * f0.y;
            acc[2] += a * f1.x; acc[3] += a * f1.y;
            acc[4] += a * f2.x; acc[5] += a * f2.y;
            acc[6] += a * f3.x; acc[7] += a * f3.y;
        }
        __syncwarp();
    }

    float rs = 1.f / ((head == 0) ? s0 : (head == 1) ? s1 : (head == 2) ? s2 : s3);
    const int f0 = lane * 8;
    size_t oi = (size_t)node * HH + f0;
    float o[8];
    #pragma unroll
    for (int k = 0; k < 8; k++) {
        float v = acc[k] * rs + bias[f0 + k];
        o[k] = (v > 0.f) ? v : expm1f(v);
    }
    *(float4*)(g_x + oi)     = make_float4(o[0], o[1], o[2], o[3]);
    *(float4*)(g_x + oi + 4) = make_float4(o[4], o[5], o[6], o[7]);
}

// ---------------- pooling ----------------
__global__ void graph_bounds_kernel(const int* __restrict__ batch) {
    int n = blockIdx.x * blockDim.x + threadIdx.x;
    if (n >= N_NODES) return;
    int b = batch[n];
    if (n == 0) {
        for (int g = 0; g <= b; g++) g_gstart[g] = 0;
    } else {
        int bp = batch[n - 1];
        for (int g = bp + 1; g <= b; g++) g_gstart[g] = n;
    }
    if (n == N_NODES - 1) {
        for (int g = b + 1; g <= N_GRAPHS; g++) g_gstart[g] = N_NODES;
    }
}
__global__ void pool_mean_kernel() {
    int g = blockIdx.x, f = threadIdx.x;
    int s = g_gstart[g], e = g_gstart[g + 1];
    float acc = 0.f;
    for (int n = s; n < e; n++)
        acc += g_x[(size_t)n * HH + f];
    g_pool[g * HH + f] = acc / (float)max(e - s, 1);
}

// ---------------- final ----------------
__global__ void final_kernel(const float* __restrict__ Wf, const float* __restrict__ bf,
                             float* __restrict__ out) {
    __shared__ float gs[HH];
    __shared__ float red[OUTF];
    int g = blockIdx.x;
    int t = threadIdx.x;
    for (int i = t; i < HH; i += OUTF) gs[i] = g_pool[g * HH + i];
    __syncthreads();
    float acc = bf[t];
    #pragma unroll 8
    for (int k = 0; k < HH; k++)
        acc += gs[k] * Wf[(size_t)k * OUTF + t];
    red[t] = acc * acc;
    __syncthreads();
    #pragma unroll
    for (int off = 64; off > 0; off >>= 1) {
        if (t < off) red[t] += red[t + off];
        __syncthreads();
    }
    float norm = fmaxf(sqrtf(red[0]), 1e-12f);
    out[(size_t)g * OUTF + t] = acc / norm;
}

// ---------------- host orchestration ----------------
extern "C" void kernel_launch(void* const* d_in, const int* in_sizes, int n_in,
                              void* d_out, int out_size) {
    const float* x     = (const float*)d_in[0];
    const int*   ei    = (const int*)d_in[1];
    const int*   batch = (const int*)d_in[2];
    const float* W[3]  = {(const float*)d_in[3],  (const float*)d_in[7],  (const float*)d_in[11]};
    const float* AS[3] = {(const float*)d_in[4],  (const float*)d_in[8],  (const float*)d_in[12]};
    const float* AD[3] = {(const float*)d_in[5],  (const float*)d_in[9],  (const float*)d_in[13]};
    const float* Bb[3] = {(const float*)d_in[6],  (const float*)d_in[10], (const float*)d_in[14]};
    const float* Wf = (const float*)d_in[15];
    const float* bf = (const float*)d_in[16];
    float* out = (float*)d_out;

    static cudaStream_t s2 = [] {
        cudaStream_t s; cudaStreamCreateWithFlags(&s, cudaStreamNonBlocking); return s;
    }();
    static cudaEvent_t eFork = [] {
        cudaEvent_t e; cudaEventCreateWithFlags(&e, cudaEventDisableTiming); return e;
    }();
    static cudaEvent_t eW = [] {
        cudaEvent_t e; cudaEventCreateWithFlags(&e, cudaEventDisableTiming); return e;
    }();
    static cudaEvent_t eCSR = [] {
        cudaEvent_t e; cudaEventCreateWithFlags(&e, cudaEventDisableTiming); return e;
    }();
    static cudaEvent_t eGB = [] {
        cudaEvent_t e; cudaEventCreateWithFlags(&e, cudaEventDisableTiming); return e;
    }();
    static bool attr_set = [] {
        cudaFuncSetAttribute(gat_gemm_kernel,
                             cudaFuncAttributeMaxDynamicSharedMemorySize, SMEM_DYN);
        return true;
    }();
    (void)attr_set;

    const int threads = 256;
    const int edge_blocks = (E_TOT + threads - 1) / threads;
    const int agg_blocks  = (N_NODES + WPB - 1) / WPB;

    cudaEventRecord(eFork, 0);
    cudaStreamWaitEvent(s2, eFork, 0);

    // launches 1-3 (side stream)
    prep_all_kernel<<<(PREP_TOTAL + threads - 1) / threads, threads, 0, s2>>>(W[0], W[1], W[2]);
    cudaEventRecord(eW, s2);
    csr_hist_kernel<<<edge_blocks, threads, 0, s2>>>(ei);
    csr_scan_kernel<<<1, 1024, 0, s2>>>();

    // launch 4: gemm layer 0 (profiler capture target)
    cudaStreamWaitEvent(0, eW, 0);
    gat_gemm_kernel<<<GEMM_BLOCKS, 512, SMEM_DYN>>>(x, 0, AS[0], AD[0], FEAT);

    // launches 5-6 (side stream)
    csr_scatter_kernel<<<edge_blocks, threads, 0, s2>>>(ei);
    cudaEventRecord(eCSR, s2);
    graph_bounds_kernel<<<(N_NODES + threads - 1) / threads, threads, 0, s2>>>(batch);
    cudaEventRecord(eGB, s2);

    cudaStreamWaitEvent(0, eCSR, 0);
    agg_kernel<<<agg_blocks, 256>>>(Bb[0]);

    gat_gemm_kernel<<<GEMM_BLOCKS, 512, SMEM_DYN>>>(nullptr, 1, AS[1], AD[1], HH);
    agg_kernel<<<agg_blocks, 256>>>(Bb[1]);

    gat_gemm_kernel<<<GEMM_BLOCKS, 512, SMEM_DYN>>>(nullptr, 2, AS[2], AD[2], HH);
    agg_kernel<<<agg_blocks, 256>>>(Bb[2]);

    cudaStreamWaitEvent(0, eGB, 0);
    pool_mean_kernel<<<N_GRAPHS, 256>>>();
    final_kernel<<<N_GRAPHS, OUTF>>>(Wf, bf, out);
}

// round 15
// speedup vs baseline: 1.3609x; 1.0193x over previous
#include <cuda_runtime.h>
#include <cuda_fp16.h>
#include <mma.h>
#include <math.h>
#include <cstdint>

using namespace nvcuda;

#define N_NODES  50000
#define TILE_M   128
#define GEMM_BLOCKS ((N_NODES + TILE_M - 1) / TILE_M)     // 392
#define N_PAD    (GEMM_BLOCKS * TILE_M)                   // 50176
#define N_EDGES  800000
#define E_TOT    (N_EDGES + N_NODES)
#define N_GRAPHS 256
#define FEAT     128
#define HID      64
#define HEADS    4
#define HH       (HID*HEADS)           // 256
#define OUTF     128
#define NEG_SLOPE 0.2f

// ---------------- scratch ----------------
__device__ __half g_h16[(size_t)N_PAD*HH];   // fp16 messages (agg gather source)
__device__ __half g_x16[(size_t)N_PAD*HH];   // fp16 layer output -> next GEMM A (pad rows 0)
__device__ float g_x[(size_t)N_PAD*HH];      // fp32 final-layer output (pooling)
__device__ __half g_w16[3*HH*HH];            // fp16 weights, [n][k], row stride 256
__device__ float g_as[N_NODES*HEADS];
__device__ float g_ad[N_NODES*HEADS];
__device__ float g_pool[N_GRAPHS*HH];
__device__ int g_gstart[N_GRAPHS+1];
// CSR
__device__ int g_deg[N_NODES];
__device__ int g_rowptr[N_NODES+1];
__device__ int g_fill[N_NODES];
__device__ int g_colidx[E_TOT];

// ---------------- helpers ----------------
__device__ __forceinline__ float warp_max(float v) {
    #pragma unroll
    for (int off = 16; off > 0; off >>= 1)
        v = fmaxf(v, __shfl_xor_sync(0xffffffffu, v, off));
    return v;
}
__device__ __forceinline__ float warp_sum(float v) {
    #pragma unroll
    for (int off = 16; off > 0; off >>= 1)
        v += __shfl_xor_sync(0xffffffffu, v, off);
    return v;
}
__device__ __forceinline__ void cp_async16(uint32_t saddr, const void* g) {
    asm volatile("cp.async.ca.shared.global [%0], [%1], 16;" :: "r"(saddr), "l"(g));
}
#define CP_COMMIT() asm volatile("cp.async.commit_group;" ::: "memory")
#define CP_WAIT0()  asm volatile("cp.async.wait_group 0;" ::: "memory")

// ---------------- fused prep: weight fp16 conversions + deg zero ----------------
#define PREP_TOTAL ((FEAT + HH + HH) * HH)   // 163840
__global__ void prep_all_kernel(const float* __restrict__ W0,
                                const float* __restrict__ W1,
                                const float* __restrict__ W2) {
    int idx = blockIdx.x * blockDim.x + threadIdx.x;
    if (idx < N_NODES) g_deg[idx] = 0;
    if (idx >= PREP_TOTAL) return;
    const float* W;
    int layer, local;
    if (idx < FEAT * HH)              { W = W0; layer = 0; local = idx; }
    else if (idx < (FEAT + HH) * HH)  { W = W1; layer = 1; local = idx - FEAT * HH; }
    else                              { W = W2; layer = 2; local = idx - (FEAT + HH) * HH; }
    int k = local >> 8, n = local & (HH - 1);
    g_w16[layer * HH * HH + n * HH + k] = __float2half_rn(W[local]);
}

// ---------------- CSR build ----------------
__global__ void csr_hist_kernel(const int* __restrict__ ei) {
    int e = blockIdx.x * blockDim.x + threadIdx.x;
    if (e >= E_TOT) return;
    int dst = (e < N_EDGES) ? ei[N_EDGES + e] : e - N_EDGES;
    atomicAdd(&g_deg[dst], 1);
}
__global__ void csr_scan_kernel() {
    __shared__ int warp_sums[32];
    __shared__ int carry_sh;
    const int tid  = threadIdx.x;
    const int lane = tid & 31;
    const int wid  = tid >> 5;
    if (tid == 0) { carry_sh = 0; g_rowptr[0] = 0; }
    __syncthreads();
    for (int base = 0; base < N_NODES; base += 1024) {
        int v = (base + tid < N_NODES) ? g_deg[base + tid] : 0;
        int x = v;
        #pragma unroll
        for (int off = 1; off < 32; off <<= 1) {
            int y = __shfl_up_sync(0xffffffffu, x, off);
            if (lane >= off) x += y;
        }
        if (lane == 31) warp_sums[wid] = x;
        __syncthreads();
        if (wid == 0) {
            int w = warp_sums[lane];
            #pragma unroll
            for (int off = 1; off < 32; off <<= 1) {
                int y = __shfl_up_sync(0xffffffffu, w, off);
                if (lane >= off) w += y;
            }
            warp_sums[lane] = w;
        }
        __syncthreads();
        int incl = x + (wid > 0 ? warp_sums[wid - 1] : 0) + carry_sh;
        if (base + tid < N_NODES) {
            g_rowptr[base + tid + 1] = incl;
            g_fill[base + tid] = incl - v;
        }
        __syncthreads();
        if (tid == 1023) carry_sh = incl;
        __syncthreads();
    }
}
__global__ void csr_scatter_kernel(const int* __restrict__ ei) {
    int e = blockIdx.x * blockDim.x + threadIdx.x;
    if (e >= E_TOT) return;
    int src, dst;
    if (e < N_EDGES) { src = ei[e]; dst = ei[N_EDGES + e]; }
    else             { src = dst = e - N_EDGES; }
    int pos = atomicAdd(&g_fill[dst], 1);
    g_colidx[pos] = src;
}

// ---------------- fp16 tensor-core GEMM (128x256), 16 warps, warp tile 32x64,
//                  KCHUNK=32 double-buffered; A via cp.async (fp16 path) or fp32 convert ----------
#define LDP 40                            // 80-byte rows
#define LDC 264
#define SMEM_DYN (TILE_M * LDC * 4)       // 135168; staging (2x30720) overlays
#define ABUF 10240                        // 128*40*2
#define BBUF 20480                        // 256*40*2
#define STGBUF (ABUF + BBUF)              // 30720
#define OFF_A(d) ((d) * STGBUF)
#define OFF_B(d) ((d) * STGBUF + ABUF)
__global__ __launch_bounds__(512)
void gat_gemm_kernel(const float* __restrict__ A_in, int layer,
                     const float* __restrict__ a_s, const float* __restrict__ a_d,
                     int K) {
    extern __shared__ char dyn[];
    float* Csm = (float*)(dyn);
    __shared__ float as_sh[HH], ad_sh[HH];

    const int tid = threadIdx.x;
    const int wid = tid >> 5;          // 0..15
    const int mw  = wid & 3;           // row group (32 rows)
    const int nw  = wid >> 2;          // col group (64 cols)
    const int rowBase = blockIdx.x * TILE_M;
    const bool a16 = (A_in == nullptr);

    const __half* __restrict__ w16 = g_w16 + (size_t)layer * HH * HH;

    if (tid < HH) { as_sh[tid] = a_s[tid]; ad_sh[tid] = a_d[tid]; }

    const uint32_t dynb = (uint32_t)__cvta_generic_to_shared(dyn);

    // staging roles (per 32-k stage)
    const int ar  = tid >> 2;            // A row 0..127
    const int ac  = (tid & 3) * 8;       // 8 elems within the 32-k chunk
    const bool aOk = (rowBase + ar) < N_NODES;   // g_x16 pad rows are zeroed anyway
    const float*  aptr   = a16 ? nullptr : (A_in + (size_t)(rowBase + ar) * K + ac);
    const __half* aptr16 = g_x16 + (size_t)(rowBase + ar) * K + ac;
    const uint32_t aRowOff = ar * 80 + ac * 2;     // bytes
    const int bn  = tid >> 1;            // B row 0..255
    const int bo  = (tid & 1) * 16;      // half offset within chunk
    const __half* bp = w16 + bn * HH + bo;
    const uint32_t bRowOff = bn * 80 + bo * 2;     // bytes

    wmma::fragment<wmma::accumulator, 16, 16, 16, float> acc[2][4];
    #pragma unroll
    for (int i = 0; i < 2; i++)
        #pragma unroll
        for (int j = 0; j < 4; j++)
            wmma::fill_fragment(acc[i][j], 0.f);

    const int nstages = K >> 5;

    auto stageA32 = [&](int d, const float4& p0, const float4& p1) {
        __half2 h0 = __floats2half2_rn(p0.x, p0.y);
        __half2 h1 = __floats2half2_rn(p0.z, p0.w);
        __half2 h2 = __floats2half2_rn(p1.x, p1.y);
        __half2 h3 = __floats2half2_rn(p1.z, p1.w);
        uint4 v;
        v.x = *(uint32_t*)&h0; v.y = *(uint32_t*)&h1;
        v.z = *(uint32_t*)&h2; v.w = *(uint32_t*)&h3;
        *(uint4*)(dyn + OFF_A(d) + aRowOff) = v;
    };
    auto issueB = [&](int d, int k0) {
        cp_async16(dynb + OFF_B(d) + bRowOff,      bp + k0);
        cp_async16(dynb + OFF_B(d) + bRowOff + 16, bp + k0 + 8);
    };

    float4 pa0, pa1;
    if (a16) {
        cp_async16(dynb + OFF_A(0) + aRowOff, aptr16);
        issueB(0, 0);
        CP_COMMIT();
    } else {
        pa0 = aOk ? *(const float4*)(aptr)     : make_float4(0.f,0.f,0.f,0.f);
        pa1 = aOk ? *(const float4*)(aptr + 4) : make_float4(0.f,0.f,0.f,0.f);
        issueB(0, 0);
        CP_COMMIT();
        stageA32(0, pa0, pa1);
        if (nstages > 1) {
            pa0 = aOk ? *(const float4*)(aptr + 32)     : make_float4(0.f,0.f,0.f,0.f);
            pa1 = aOk ? *(const float4*)(aptr + 32 + 4) : make_float4(0.f,0.f,0.f,0.f);
        }
    }

    for (int c = 0; c < nstages; c++) {
        const int d = c & 1;
        CP_WAIT0();
        __syncthreads();
        if (c + 1 < nstages) {
            int k1 = (c + 1) << 5;
            if (a16) {
                cp_async16(dynb + OFF_A(d ^ 1) + aRowOff, aptr16 + k1);
                issueB(d ^ 1, k1);
                CP_COMMIT();
            } else {
                issueB(d ^ 1, k1);
                CP_COMMIT();
                stageA32(d ^ 1, pa0, pa1);
                if (c + 2 < nstages) {
                    int k2 = (c + 2) << 5;
                    pa0 = aOk ? *(const float4*)(aptr + k2)     : make_float4(0.f,0.f,0.f,0.f);
                    pa1 = aOk ? *(const float4*)(aptr + k2 + 4) : make_float4(0.f,0.f,0.f,0.f);
                }
            }
        }
        const __half* Ah = (const __half*)(dyn + OFF_A(d));
        const __half* Bh = (const __half*)(dyn + OFF_B(d));

        #pragma unroll
        for (int kk = 0; kk < 2; kk++) {
            wmma::fragment<wmma::matrix_a, 16, 16, 16, __half, wmma::row_major> a[2];
            #pragma unroll
            for (int i = 0; i < 2; i++)
                wmma::load_matrix_sync(a[i], Ah + (mw * 32 + i * 16) * LDP + kk * 16, LDP);
            #pragma unroll
            for (int j = 0; j < 4; j++) {
                wmma::fragment<wmma::matrix_b, 16, 16, 16, __half, wmma::col_major> b;
                wmma::load_matrix_sync(b, Bh + (nw * 64 + j * 16) * LDP + kk * 16, LDP);
                #pragma unroll
                for (int i = 0; i < 2; i++)
                    wmma::mma_sync(acc[i][j], a[i], b, acc[i][j]);
            }
        }
    }
    __syncthreads();   // staging reads done before C overlays

    #pragma unroll
    for (int i = 0; i < 2; i++)
        #pragma unroll
        for (int j = 0; j < 4; j++) {
            float* cp = Csm + (size_t)(mw * 32 + i * 16) * LDC + nw * 64 + j * 16;
            wmma::store_matrix_sync(cp, acc[i][j], LDC, wmma::mem_row_major);
        }
    __syncthreads();

    // epilogue: alphas dot + fp16 message pack
    int rl = tid >> 2;
    int hd = tid & 3;
    int r  = rowBase + rl;
    if (r < N_NODES) {
        const float* hp = Csm + (size_t)rl * LDC + hd * HID;
        __half* h16p = g_h16 + (size_t)r * HH + hd * HID;
        const float* sp = as_sh + hd * HID;
        const float* dp = ad_sh + hd * HID;
        float vs = 0.f, vd = 0.f;
        #pragma unroll
        for (int c = 0; c < HID; c += 4) {
            float4 v = *(const float4*)(hp + c);
            vs += v.x * sp[c] + v.y * sp[c+1] + v.z * sp[c+2] + v.w * sp[c+3];
            vd += v.x * dp[c] + v.y * dp[c+1] + v.z * dp[c+2] + v.w * dp[c+3];
            uint2 pk;
            __half2 p0 = __floats2half2_rn(v.x, v.y);
            __half2 p1 = __floats2half2_rn(v.z, v.w);
            pk.x = *(uint32_t*)&p0;
            pk.y = *(uint32_t*)&p1;
            *(uint2*)(h16p + c) = pk;
        }
        g_as[r * HEADS + hd] = vs;
        g_ad[r * HEADS + hd] = vd;
    }
}

// ---------------- warp-per-node flash softmax + aggregation (fp16 gathers) ----------------
#define WPB 8
__global__ __launch_bounds__(256)
void agg_kernel(const float* __restrict__ bias, int last) {
    const int wrp  = threadIdx.x >> 5;
    const int lane = threadIdx.x & 31;
    const int node = blockIdx.x * WPB + wrp;
    if (node >= N_NODES) return;

    __shared__ float s_al[WPB][32 * 4];
    __shared__ int   s_src[WPB][32];

    const int start = g_rowptr[node];
    const int end   = g_rowptr[node + 1];

    const float4 ad4 = *(const float4*)(g_ad + node * HEADS);

    const int head = lane >> 3;
    float m0 = -INFINITY, m1 = -INFINITY, m2 = -INFINITY, m3 = -INFINITY;
    float s0 = 0.f, s1 = 0.f, s2 = 0.f, s3 = 0.f;
    float acc[8] = {0.f, 0.f, 0.f, 0.f, 0.f, 0.f, 0.f, 0.f};

    for (int c0 = start; c0 < end; c0 += 32) {
        const int len = min(32, end - c0);

        float e0 = -INFINITY, e1 = -INFINITY, e2 = -INFINITY, e3 = -INFINITY;
        if (lane < len) {
            int s = g_colidx[c0 + lane];
            s_src[wrp][lane] = s;
            float4 as4 = *(const float4*)(g_as + s * HEADS);
            e0 = as4.x + ad4.x; e0 = (e0 > 0.f) ? e0 : NEG_SLOPE * e0;
            e1 = as4.y + ad4.y; e1 = (e1 > 0.f) ? e1 : NEG_SLOPE * e1;
            e2 = as4.z + ad4.z; e2 = (e2 > 0.f) ? e2 : NEG_SLOPE * e2;
            e3 = as4.w + ad4.w; e3 = (e3 > 0.f) ? e3 : NEG_SLOPE * e3;
        }
        float n0 = fmaxf(m0, warp_max(e0));
        float n1 = fmaxf(m1, warp_max(e1));
        float n2 = fmaxf(m2, warp_max(e2));
        float n3 = fmaxf(m3, warp_max(e3));
        float sc0 = expf(m0 - n0), sc1 = expf(m1 - n1);
        float sc2 = expf(m2 - n2), sc3 = expf(m3 - n3);
        m0 = n0; m1 = n1; m2 = n2; m3 = n3;

        float q0 = (lane < len) ? expf(e0 - m0) : 0.f;
        float q1 = (lane < len) ? expf(e1 - m1) : 0.f;
        float q2 = (lane < len) ? expf(e2 - m2) : 0.f;
        float q3 = (lane < len) ? expf(e3 - m3) : 0.f;
        s_al[wrp][lane * 4 + 0] = q0;
        s_al[wrp][lane * 4 + 1] = q1;
        s_al[wrp][lane * 4 + 2] = q2;
        s_al[wrp][lane * 4 + 3] = q3;
        s0 = s0 * sc0 + warp_sum(q0);
        s1 = s1 * sc1 + warp_sum(q1);
        s2 = s2 * sc2 + warp_sum(q2);
        s3 = s3 * sc3 + warp_sum(q3);

        float accsc = (head == 0) ? sc0 : (head == 1) ? sc1 : (head == 2) ? sc2 : sc3;
        #pragma unroll
        for (int k = 0; k < 8; k++) acc[k] *= accsc;
        __syncwarp();

        #pragma unroll 4
        for (int j = 0; j < len; j++) {
            float a = s_al[wrp][j * 4 + head];
            uint4 u = *(const uint4*)(g_h16 + (size_t)s_src[wrp][j] * HH + lane * 8);
            float2 f0 = __half22float2(*(__half2*)&u.x);
            float2 f1 = __half22float2(*(__half2*)&u.y);
            float2 f2 = __half22float2(*(__half2*)&u.z);
            float2 f3 = __half22float2(*(__half2*)&u.w);
            acc[0] += a * f0.x; acc[1] += a * f0.y;
            acc[2] += a * f1.x; acc[3] += a * f1.y;
            acc[4] += a * f2.x; acc[5] += a * f2.y;
            acc[6] += a * f3.x; acc[7] += a * f3.y;
        }
        __syncwarp();
    }

    float rs = 1.f / ((head == 0) ? s0 : (head == 1) ? s1 : (head == 2) ? s2 : s3);
    const int f0 = lane * 8;
    size_t oi = (size_t)node * HH + f0;
    float o[8];
    #pragma unroll
    for (int k = 0; k < 8; k++) {
        float v = acc[k] * rs + bias[f0 + k];
        o[k] = (v > 0.f) ? v : expm1f(v);
    }
    if (last) {
        *(float4*)(g_x + oi)     = make_float4(o[0], o[1], o[2], o[3]);
        *(float4*)(g_x + oi + 4) = make_float4(o[4], o[5], o[6], o[7]);
    } else {
        __half2 p0 = __floats2half2_rn(o[0], o[1]);
        __half2 p1 = __floats2half2_rn(o[2], o[3]);
        __half2 p2 = __floats2half2_rn(o[4], o[5]);
        __half2 p3 = __floats2half2_rn(o[6], o[7]);
        uint4 v;
        v.x = *(uint32_t*)&p0; v.y = *(uint32_t*)&p1;
        v.z = *(uint32_t*)&p2; v.w = *(uint32_t*)&p3;
        *(uint4*)(g_x16 + oi) = v;
    }
}

// ---------------- pooling ----------------
__global__ void graph_bounds_kernel(const int* __restrict__ batch) {
    int n = blockIdx.x * blockDim.x + threadIdx.x;
    if (n >= N_NODES) return;
    int b = batch[n];
    if (n == 0) {
        for (int g = 0; g <= b; g++) g_gstart[g] = 0;
    } else {
        int bp = batch[n - 1];
        for (int g = bp + 1; g <= b; g++) g_gstart[g] = n;
    }
    if (n == N_NODES - 1) {
        for (int g = b + 1; g <= N_GRAPHS; g++) g_gstart[g] = N_NODES;
    }
}
__global__ void pool_mean_kernel() {
    int g = blockIdx.x, f = threadIdx.x;
    int s = g_gstart[g], e = g_gstart[g + 1];
    float acc = 0.f;
    for (int n = s; n < e; n++)
        acc += g_x[(size_t)n * HH + f];
    g_pool[g * HH + f] = acc / (float)max(e - s, 1);
}

// ---------------- final ----------------
__global__ void final_kernel(const float* __restrict__ Wf, const float* __restrict__ bf,
                             float* __restrict__ out) {
    __shared__ float gs[HH];
    __shared__ float red[OUTF];
    int g = blockIdx.x;
    int t = threadIdx.x;
    for (int i = t; i < HH; i += OUTF) gs[i] = g_pool[g * HH + i];
    __syncthreads();
    float acc = bf[t];
    #pragma unroll 8
    for (int k = 0; k < HH; k++)
        acc += gs[k] * Wf[(size_t)k * OUTF + t];
    red[t] = acc * acc;
    __syncthreads();
    #pragma unroll
    for (int off = 64; off > 0; off >>= 1) {
        if (t < off) red[t] += red[t + off];
        __syncthreads();
    }
    float norm = fmaxf(sqrtf(red[0]), 1e-12f);
    out[(size_t)g * OUTF + t] = acc / norm;
}

// ---------------- host orchestration ----------------
extern "C" void kernel_launch(void* const* d_in, const int* in_sizes, int n_in,
                              void* d_out, int out_size) {
    const float* x     = (const float*)d_in[0];
    const int*   ei    = (const int*)d_in[1];
    const int*   batch = (const int*)d_in[2];
    const float* W[3]  = {(const float*)d_in[3],  (const float*)d_in[7],  (const float*)d_in[11]};
    const float* AS[3] = {(const float*)d_in[4],  (const float*)d_in[8],  (const float*)d_in[12]};
    const float* AD[3] = {(const float*)d_in[5],  (const float*)d_in[9],  (const float*)d_in[13]};
    const float* Bb[3] = {(const float*)d_in[6],  (const float*)d_in[10], (const float*)d_in[14]};
    const float* Wf = (const float*)d_in[15];
    const float* bf = (const float*)d_in[16];
    float* out = (float*)d_out;

    static cudaStream_t s2 = [] {
        cudaStream_t s; cudaStreamCreateWithFlags(&s, cudaStreamNonBlocking); return s;
    }();
    static cudaEvent_t eFork = [] {
        cudaEvent_t e; cudaEventCreateWithFlags(&e, cudaEventDisableTiming); return e;
    }();
    static cudaEvent_t eW = [] {
        cudaEvent_t e; cudaEventCreateWithFlags(&e, cudaEventDisableTiming); return e;
    }();
    static cudaEvent_t eCSR = [] {
        cudaEvent_t e; cudaEventCreateWithFlags(&e, cudaEventDisableTiming); return e;
    }();
    static cudaEvent_t eGB = [] {
        cudaEvent_t e; cudaEventCreateWithFlags(&e, cudaEventDisableTiming); return e;
    }();
    static bool attr_set = [] {
        cudaFuncSetAttribute(gat_gemm_kernel,
                             cudaFuncAttributeMaxDynamicSharedMemorySize, SMEM_DYN);
        return true;
    }();
    (void)attr_set;

    const int threads = 256;
    const int edge_blocks = (E_TOT + threads - 1) / threads;
    const int agg_blocks  = (N_NODES + WPB - 1) / WPB;

    cudaEventRecord(eFork, 0);
    cudaStreamWaitEvent(s2, eFork, 0);

    // launches 1-3 (side stream)
    prep_all_kernel<<<(PREP_TOTAL + threads - 1) / threads, threads, 0, s2>>>(W[0], W[1], W[2]);
    cudaEventRecord(eW, s2);
    csr_hist_kernel<<<edge_blocks, threads, 0, s2>>>(ei);
    csr_scan_kernel<<<1, 1024, 0, s2>>>();

    // launch 4: gemm layer 0 (profiler capture target)
    cudaStreamWaitEvent(0, eW, 0);
    gat_gemm_kernel<<<GEMM_BLOCKS, 512, SMEM_DYN>>>(x, 0, AS[0], AD[0], FEAT);

    // launches 5-6 (side stream)
    csr_scatter_kernel<<<edge_blocks, threads, 0, s2>>>(ei);
    cudaEventRecord(eCSR, s2);
    graph_bounds_kernel<<<(N_NODES + threads - 1) / threads, threads, 0, s2>>>(batch);
    cudaEventRecord(eGB, s2);

    cudaStreamWaitEvent(0, eCSR, 0);
    agg_kernel<<<agg_blocks, 256>>>(Bb[0], 0);

    gat_gemm_kernel<<<GEMM_BLOCKS, 512, SMEM_DYN>>>(nullptr, 1, AS[1], AD[1], HH);
    agg_kernel<<<agg_blocks, 256>>>(Bb[1], 0);

    gat_gemm_kernel<<<GEMM_BLOCKS, 512, SMEM_DYN>>>(nullptr, 2, AS[2], AD[2], HH);
    agg_kernel<<<agg_blocks, 256>>>(Bb[2], 1);

    cudaStreamWaitEvent(0, eGB, 0);
    pool_mean_kernel<<<N_GRAPHS, 256>>>();
    final_kernel<<<N_GRAPHS, OUTF>>>(Wf, bf, out);
}